// round 2
// baseline (speedup 1.0000x reference)
#include <cuda_runtime.h>
#include <math.h>

#define B_ 2
#define N_ 65536
#define DP 64
#define DM 128
#define NPTS (B_*N_)
#define NCHUNK 64
#define SCALE_F 0.088388347648318441f  /* 1/sqrt(128) */

// ---------------- device scratch (no allocations allowed) ----------------
__device__ float g_gv[(size_t)NPTS * DM];   // v + pos_enc   (64 MB)
__device__ float g_Ws[DP * DM];             // fc1 @ (wq - wk)
__device__ float g_Wv[DP * DM];             // fc1 @ wv
__device__ float g_bs[DM];
__device__ float g_bv[DM];
__device__ float g_part[B_ * DM * NCHUNK * 2];
__device__ float g_ms[B_ * DM * 2];

// ---------------- k0: fold fc1 into (wq-wk) and wv ----------------
__global__ void k0_fold(const float* __restrict__ fc1w, const float* __restrict__ fc1b,
                        const float* __restrict__ wq, const float* __restrict__ wk,
                        const float* __restrict__ wv)
{
    int idx = blockIdx.x * 256 + threadIdx.x;     // 0..8191
    int m = idx >> 7, j = idx & 127;
    float as = 0.f, av = 0.f;
    for (int k = 0; k < DM; k++) {
        float f = fc1w[m * DM + k];
        as += f * (wq[k * DM + j] - wk[k * DM + j]);
        av += f * wv[k * DM + j];
    }
    g_Ws[idx] = as;
    g_Wv[idx] = av;
    if (blockIdx.x == 0 && threadIdx.x < DM) {
        int jj = threadIdx.x;
        float bs = 0.f, bv = 0.f;
        for (int k = 0; k < DM; k++) {
            float fb = fc1b[k];
            bs += fb * (wq[k * DM + jj] - wk[k * DM + jj]);
            bv += fb * wv[k * DM + jj];
        }
        g_bs[jj] = bs;
        g_bv[jj] = bv;
    }
}

// ---------------- shared GEMM tile: 8x8 outputs per thread ----------------
__device__ __forceinline__ void gemm_tile(const float* __restrict__ A, int lda,
                                          const float* __restrict__ W, int K,
                                          int r0, int c0, float acc[8][8])
{
    #pragma unroll
    for (int i = 0; i < 8; i++)
        #pragma unroll
        for (int j = 0; j < 8; j++) acc[i][j] = 0.f;
    #pragma unroll 4
    for (int k = 0; k < K; k++) {
        float4 w0 = *(const float4*)(W + k * DM + c0);
        float4 w1 = *(const float4*)(W + k * DM + c0 + 4);
        #pragma unroll
        for (int i = 0; i < 8; i++) {
            float a = A[(r0 + i) * lda + k];
            acc[i][0] += a * w0.x; acc[i][1] += a * w0.y;
            acc[i][2] += a * w0.z; acc[i][3] += a * w0.w;
            acc[i][4] += a * w1.x; acc[i][5] += a * w1.y;
            acc[i][6] += a * w1.z; acc[i][7] += a * w1.w;
        }
    }
}

// ---------------- k1: main per-point chain (128 points / CTA) ----------------
__global__ void __launch_bounds__(256) k1_main(
    const float* __restrict__ xyz, const float* __restrict__ feat,
    const float* __restrict__ d1w, const float* __restrict__ d1b,
    const float* __restrict__ d2w, const float* __restrict__ d2b,
    const float* __restrict__ g1w, const float* __restrict__ g1b,
    const float* __restrict__ g2w, const float* __restrict__ g2b,
    float* __restrict__ aout)
{
    extern __shared__ float smd[];
    float* Wsm = smd;            // 128*128
    float* Pm  = smd + 16384;    // 128*128 : pos, then S
    float* Tm  = smd + 32768;    // 128*128 : hrel, then features, then H
    __shared__ float d1s[384], xyzs[384];
    __shared__ float bd1[DM], bd2[DM], bg1[DM], bg2[DM], bss[DM], bvv[DM];

    const int tid = threadIdx.x;
    const int tx = tid & 15, ty = tid >> 4;
    const int r0 = ty * 8, c0 = tx * 8;
    const int p0 = blockIdx.x * 128;

    for (int i = tid; i < 384; i += 256) { d1s[i] = d1w[i]; xyzs[i] = xyz[p0 * 3 + i]; }
    if (tid < DM) {
        bd1[tid] = d1b[tid]; bd2[tid] = d2b[tid];
        bg1[tid] = g1b[tid]; bg2[tid] = g2b[tid];
        bss[tid] = g_bs[tid]; bvv[tid] = g_bv[tid];
    }
    for (int i = tid * 4; i < 16384; i += 1024)
        *(float4*)(Wsm + i) = *(const float4*)(d2w + i);
    __syncthreads();

    // hrel = relu(xyz @ d1 + d1b)  -> Tm
    #pragma unroll
    for (int i = 0; i < 8; i++) {
        int p = r0 + i;
        float x0 = xyzs[p * 3], x1 = xyzs[p * 3 + 1], x2 = xyzs[p * 3 + 2];
        #pragma unroll
        for (int j = 0; j < 8; j++) {
            int c = c0 + j;
            float h = x0 * d1s[c] + x1 * d1s[DM + c] + x2 * d1s[2 * DM + c] + bd1[c];
            Tm[p * DM + c] = fmaxf(h, 0.f);
        }
    }
    __syncthreads();

    float acc[8][8];

    // pos = hrel @ d2 + d2b  -> Pm
    gemm_tile(Tm, DM, Wsm, DM, r0, c0, acc);
    #pragma unroll
    for (int i = 0; i < 8; i++)
        #pragma unroll
        for (int j = 0; j < 8; j++)
            Pm[(r0 + i) * DM + c0 + j] = acc[i][j] + bd2[c0 + j];
    __syncthreads();

    // load features tile (128x64) -> Tm, Wv -> Wsm
    for (int i = tid * 4; i < 8192; i += 1024) {
        *(float4*)(Tm + i)  = *(const float4*)(feat + p0 * 64 + i);
        *(float4*)(Wsm + i) = *(const float4*)(g_Wv + i);
    }
    __syncthreads();

    // gv = f @ Wv + bv + pos  -> global
    gemm_tile(Tm, 64, Wsm, 64, r0, c0, acc);
    #pragma unroll
    for (int i = 0; i < 8; i++)
        #pragma unroll
        for (int j = 0; j < 8; j++)
            g_gv[(size_t)(p0 + r0 + i) * DM + c0 + j] =
                acc[i][j] + bvv[c0 + j] + Pm[(r0 + i) * DM + c0 + j];
    __syncthreads();

    for (int i = tid * 4; i < 8192; i += 1024)
        *(float4*)(Wsm + i) = *(const float4*)(g_Ws + i);
    __syncthreads();

    // S = f @ Ws + bs + pos  -> Pm (each thread RMWs only its own elements)
    gemm_tile(Tm, 64, Wsm, 64, r0, c0, acc);
    #pragma unroll
    for (int i = 0; i < 8; i++)
        #pragma unroll
        for (int j = 0; j < 8; j++) {
            int o = (r0 + i) * DM + c0 + j;
            Pm[o] = acc[i][j] + bss[c0 + j] + Pm[o];
        }
    __syncthreads();

    for (int i = tid * 4; i < 16384; i += 1024)
        *(float4*)(Wsm + i) = *(const float4*)(g1w + i);
    __syncthreads();

    // H = relu(S @ g1 + g1b) -> Tm
    gemm_tile(Pm, DM, Wsm, DM, r0, c0, acc);
    #pragma unroll
    for (int i = 0; i < 8; i++)
        #pragma unroll
        for (int j = 0; j < 8; j++)
            Tm[(r0 + i) * DM + c0 + j] = fmaxf(acc[i][j] + bg1[c0 + j], 0.f);
    __syncthreads();

    for (int i = tid * 4; i < 16384; i += 1024)
        *(float4*)(Wsm + i) = *(const float4*)(g2w + i);
    __syncthreads();

    // A = (H @ g2 + g2b) * SCALE -> aout (pre-softmax logits, in-place later)
    gemm_tile(Tm, DM, Wsm, DM, r0, c0, acc);
    #pragma unroll
    for (int i = 0; i < 8; i++)
        #pragma unroll
        for (int j = 0; j < 8; j++)
            aout[(size_t)(p0 + r0 + i) * DM + c0 + j] =
                (acc[i][j] + bg2[c0 + j]) * SCALE_F;
}

// ---------------- k2a: per-chunk online (max,sum) over N ----------------
__global__ void k2a_stats(const float* __restrict__ aout)
{
    int tx = threadIdx.x, ty = threadIdx.y;
    int c = blockIdx.x * 32 + tx;
    int chunk = blockIdx.y;
    int b = blockIdx.z;
    const float* base = aout + (size_t)b * N_ * DM + c;
    const int rows = N_ / NCHUNK;         // 1024
    int n0 = chunk * rows;

    float m = -3.4e38f, s = 0.f;
    #pragma unroll 4
    for (int n = n0 + ty; n < n0 + rows; n += 8) {
        float a = base[(size_t)n * DM];
        if (a > m) { s *= expf(m - a); m = a; }
        s += expf(a - m);
    }
    __shared__ float smm[8][32], sms[8][32];
    smm[ty][tx] = m; sms[ty][tx] = s;
    __syncthreads();
    if (ty == 0) {
        float M = m, S = s;
        #pragma unroll
        for (int r = 1; r < 8; r++) {
            float m2 = smm[r][tx], s2 = sms[r][tx];
            float nM = fmaxf(M, m2);
            S = S * expf(M - nM) + s2 * expf(m2 - nM);
            M = nM;
        }
        int o = ((b * DM + c) * NCHUNK + chunk) * 2;
        g_part[o] = M; g_part[o + 1] = S;
    }
}

// ---------------- k2b: combine chunk partials ----------------
__global__ void k2b_combine()
{
    int idx = threadIdx.x;   // 0..255 = b*128 + c
    const float* p = g_part + (size_t)idx * NCHUNK * 2;
    float M = -3.4e38f;
    for (int ch = 0; ch < NCHUNK; ch++) M = fmaxf(M, p[ch * 2]);
    float S = 0.f;
    for (int ch = 0; ch < NCHUNK; ch++) S += p[ch * 2 + 1] * expf(p[ch * 2] - M);
    g_ms[idx * 2] = M;
    g_ms[idx * 2 + 1] = 1.f / S;
}

// ---------------- k3: softmax normalize (in place) + gate + fc2 + residual ----
__global__ void __launch_bounds__(256) k3_out(
    const float* __restrict__ feat,
    const float* __restrict__ fc2w, const float* __restrict__ fc2b,
    float* __restrict__ res, float* __restrict__ aout)
{
    extern __shared__ float smd[];
    float* fc2s = smd;            // 128*64
    float* tsm  = smd + 8192;     // 128*128
    __shared__ float msm[DM], rsm[DM], fb[64];

    int tid = threadIdx.x;
    int p0 = blockIdx.x * 128;
    int b = p0 >> 16;             // N_ = 65536

    for (int i = tid * 4; i < 8192; i += 1024)
        *(float4*)(fc2s + i) = *(const float4*)(fc2w + i);
    if (tid < DM) {
        msm[tid] = g_ms[(b * DM + tid) * 2];
        rsm[tid] = g_ms[(b * DM + tid) * 2 + 1];
    }
    if (tid < 64) fb[tid] = fc2b[tid];
    __syncthreads();

    for (int idx = tid; idx < 16384; idx += 256) {
        int c = idx & 127;
        size_t go = (size_t)p0 * DM + idx;
        float a = aout[go];
        float e = expf(a - msm[c]) * rsm[c];
        aout[go] = e;                     // final attn output
        tsm[idx] = e * g_gv[go];          // gated values
    }
    __syncthreads();

    int tx = tid & 15, ty = tid >> 4;
    int r0 = ty * 8, c0 = tx * 4;
    float acc[8][4] = {};
    #pragma unroll 4
    for (int k = 0; k < DM; k++) {
        float4 w = *(const float4*)(fc2s + k * 64 + c0);
        #pragma unroll
        for (int i = 0; i < 8; i++) {
            float a = tsm[(r0 + i) * DM + k];
            acc[i][0] += a * w.x; acc[i][1] += a * w.y;
            acc[i][2] += a * w.z; acc[i][3] += a * w.w;
        }
    }
    #pragma unroll
    for (int i = 0; i < 8; i++)
        #pragma unroll
        for (int j = 0; j < 4; j++)
            res[(size_t)(p0 + r0 + i) * 64 + c0 + j] =
                acc[i][j] + fb[c0 + j] + feat[(size_t)(p0 + r0 + i) * 64 + c0 + j];
}

// ---------------- launch ----------------
extern "C" void kernel_launch(void* const* d_in, const int* in_sizes, int n_in,
                              void* d_out, int out_size)
{
    const float* xyz  = (const float*)d_in[0];
    const float* feat = (const float*)d_in[1];
    const float* fc1w = (const float*)d_in[2];
    const float* fc1b = (const float*)d_in[3];
    const float* fc2w = (const float*)d_in[4];
    const float* fc2b = (const float*)d_in[5];
    const float* d1w  = (const float*)d_in[6];
    const float* d1b  = (const float*)d_in[7];
    const float* d2w  = (const float*)d_in[8];
    const float* d2b  = (const float*)d_in[9];
    const float* g1w  = (const float*)d_in[10];
    const float* g1b  = (const float*)d_in[11];
    const float* g2w  = (const float*)d_in[12];
    const float* g2b  = (const float*)d_in[13];
    const float* wq   = (const float*)d_in[14];
    const float* wk   = (const float*)d_in[15];
    const float* wv   = (const float*)d_in[16];

    float* res  = (float*)d_out;                       // [2,65536,64]
    float* aout = (float*)d_out + (size_t)NPTS * 64;   // [2,65536,128]

    cudaFuncSetAttribute(k1_main, cudaFuncAttributeMaxDynamicSharedMemorySize, 196608);
    cudaFuncSetAttribute(k3_out,  cudaFuncAttributeMaxDynamicSharedMemorySize, 98304);

    k0_fold<<<32, 256>>>(fc1w, fc1b, wq, wk, wv);
    k1_main<<<NPTS / 128, 256, 196608>>>(xyz, feat, d1w, d1b, d2w, d2b,
                                         g1w, g1b, g2w, g2b, aout);
    dim3 g2(DM / 32, NCHUNK, B_), b2(32, 8);
    k2a_stats<<<g2, b2>>>(aout);
    k2b_combine<<<1, 256>>>();
    k3_out<<<NPTS / 128, 256, 98304>>>(feat, fc2w, fc2b, res, aout);
}

// round 4
// speedup vs baseline: 1.0620x; 1.0620x over previous
#include <cuda_runtime.h>
#include <math.h>

#define B_ 2
#define N_ 65536
#define DP 64
#define DM 128
#define NPTS (B_*N_)
#define NCHUNK 64
#define SCALE_F 0.088388347648318441f  /* 1/sqrt(128) */

// ---------------- device scratch (no allocations allowed) ----------------
__device__ float g_gv[(size_t)NPTS * DM];   // v + pos_enc   (64 MB)
__device__ float g_Ws[DP * DM];             // fc1 @ (wq - wk)
__device__ float g_Wv[DP * DM];             // fc1 @ wv
__device__ float g_bs[DM];
__device__ float g_bv[DM];
__device__ float g_part[B_ * DM * NCHUNK * 2];
__device__ float g_ms[B_ * DM * 2];

// ---------------- packed f32x2 helpers (sm_103a FFMA2) ----------------
__device__ __forceinline__ unsigned long long pk2(float x, float y) {
    unsigned long long r;
    asm("mov.b64 %0, {%1, %2};" : "=l"(r) : "f"(x), "f"(y));
    return r;
}
__device__ __forceinline__ void fma2(unsigned long long& d,
                                     unsigned long long a, unsigned long long b) {
    asm("fma.rn.f32x2 %0, %1, %2, %0;" : "+l"(d) : "l"(a), "l"(b));
}
__device__ __forceinline__ void upk2(unsigned long long v, float& x, float& y) {
    asm("mov.b64 {%0, %1}, %2;" : "=f"(x), "=f"(y) : "l"(v));
}

// ---------------- k0: fold fc1 into (wq-wk) and wv ----------------
__global__ void k0_fold(const float* __restrict__ fc1w, const float* __restrict__ fc1b,
                        const float* __restrict__ wq, const float* __restrict__ wk,
                        const float* __restrict__ wv)
{
    int idx = blockIdx.x * 256 + threadIdx.x;     // 0..8191
    int m = idx >> 7, j = idx & 127;
    float as = 0.f, av = 0.f;
    for (int k = 0; k < DM; k++) {
        float f = fc1w[m * DM + k];
        as += f * (wq[k * DM + j] - wk[k * DM + j]);
        av += f * wv[k * DM + j];
    }
    g_Ws[idx] = as;
    g_Wv[idx] = av;
    if (blockIdx.x == 0 && threadIdx.x < DM) {
        int jj = threadIdx.x;
        float bs = 0.f, bv = 0.f;
        for (int k = 0; k < DM; k++) {
            float fb = fc1b[k];
            bs += fb * (wq[k * DM + jj] - wk[k * DM + jj]);
            bv += fb * wv[k * DM + jj];
        }
        g_bs[jj] = bs;
        g_bv[jj] = bv;
    }
}

// ---------------- shared GEMM tile: 8x8 outputs per thread, FFMA2 ----------
// W has row stride ldw (floats); c0 must be 8-float (32B) aligned.
__device__ __forceinline__ void gemm_tile2(const float* __restrict__ A, int lda,
                                           const float* __restrict__ W, int ldw, int K,
                                           int r0, int c0, float acc[8][8])
{
    unsigned long long acc2[8][4];
    #pragma unroll
    for (int i = 0; i < 8; i++)
        #pragma unroll
        for (int j = 0; j < 4; j++) acc2[i][j] = 0ull;

    #pragma unroll 2
    for (int k = 0; k < K; k += 2) {
        ulonglong2 w00 = *(const ulonglong2*)(W + (size_t)k * ldw + c0);
        ulonglong2 w01 = *(const ulonglong2*)(W + (size_t)k * ldw + c0 + 4);
        ulonglong2 w10 = *(const ulonglong2*)(W + (size_t)(k + 1) * ldw + c0);
        ulonglong2 w11 = *(const ulonglong2*)(W + (size_t)(k + 1) * ldw + c0 + 4);
        #pragma unroll
        for (int i = 0; i < 8; i++) {
            float2 a2 = *(const float2*)(A + (r0 + i) * lda + k);
            unsigned long long a0 = pk2(a2.x, a2.x);
            unsigned long long a1 = pk2(a2.y, a2.y);
            fma2(acc2[i][0], a0, w00.x); fma2(acc2[i][1], a0, w00.y);
            fma2(acc2[i][2], a0, w01.x); fma2(acc2[i][3], a0, w01.y);
            fma2(acc2[i][0], a1, w10.x); fma2(acc2[i][1], a1, w10.y);
            fma2(acc2[i][2], a1, w11.x); fma2(acc2[i][3], a1, w11.y);
        }
    }
    #pragma unroll
    for (int i = 0; i < 8; i++)
        #pragma unroll
        for (int j = 0; j < 4; j++)
            upk2(acc2[i][j], acc[i][2 * j], acc[i][2 * j + 1]);
}

// ---------------- k1: main per-point chain (128 points / CTA) ----------------
__global__ void __launch_bounds__(256) k1_main(
    const float* __restrict__ xyz, const float* __restrict__ feat,
    const float* __restrict__ d1w, const float* __restrict__ d1b,
    const float* __restrict__ d2w, const float* __restrict__ d2b,
    const float* __restrict__ g1w, const float* __restrict__ g1b,
    const float* __restrict__ g2w, const float* __restrict__ g2b,
    float* __restrict__ aout)
{
    extern __shared__ float smd[];
    float* Wsm = smd;            // 128*128
    float* Pm  = smd + 16384;    // 128*128 : pos, then S
    float* Tm  = smd + 32768;    // 128*128 : hrel, then features, then H
    __shared__ float d1s[384], xyzs[384];
    __shared__ float bd1[DM], bd2[DM], bg1[DM], bg2[DM], bss[DM], bvv[DM];

    const int tid = threadIdx.x;
    const int tx = tid & 15, ty = tid >> 4;
    const int r0 = ty * 8, c0 = tx * 8;
    const int p0 = blockIdx.x * 128;

    for (int i = tid; i < 384; i += 256) { d1s[i] = d1w[i]; xyzs[i] = xyz[p0 * 3 + i]; }
    if (tid < DM) {
        bd1[tid] = d1b[tid]; bd2[tid] = d2b[tid];
        bg1[tid] = g1b[tid]; bg2[tid] = g2b[tid];
        bss[tid] = g_bs[tid]; bvv[tid] = g_bv[tid];
    }
    for (int i = tid * 4; i < 16384; i += 1024)
        *(float4*)(Wsm + i) = *(const float4*)(d2w + i);
    __syncthreads();

    // hrel = relu(xyz @ d1 + d1b)  -> Tm
    #pragma unroll
    for (int i = 0; i < 8; i++) {
        int p = r0 + i;
        float x0 = xyzs[p * 3], x1 = xyzs[p * 3 + 1], x2 = xyzs[p * 3 + 2];
        #pragma unroll
        for (int j = 0; j < 8; j++) {
            int c = c0 + j;
            float h = x0 * d1s[c] + x1 * d1s[DM + c] + x2 * d1s[2 * DM + c] + bd1[c];
            Tm[p * DM + c] = fmaxf(h, 0.f);
        }
    }
    __syncthreads();

    float acc[8][8];

    // pos = hrel @ d2 + d2b  -> Pm
    gemm_tile2(Tm, DM, Wsm, DM, DM, r0, c0, acc);
    #pragma unroll
    for (int i = 0; i < 8; i++)
        #pragma unroll
        for (int j = 0; j < 8; j++)
            Pm[(r0 + i) * DM + c0 + j] = acc[i][j] + bd2[c0 + j];
    __syncthreads();

    // load features tile (128x64) -> Tm, Wv -> Wsm
    for (int i = tid * 4; i < 8192; i += 1024) {
        *(float4*)(Tm + i)  = *(const float4*)(feat + p0 * 64 + i);
        *(float4*)(Wsm + i) = *(const float4*)(g_Wv + i);
    }
    __syncthreads();

    // gv = f @ Wv + bv + pos  -> global
    gemm_tile2(Tm, 64, Wsm, DM, 64, r0, c0, acc);
    #pragma unroll
    for (int i = 0; i < 8; i++)
        #pragma unroll
        for (int j = 0; j < 8; j++)
            g_gv[(size_t)(p0 + r0 + i) * DM + c0 + j] =
                acc[i][j] + bvv[c0 + j] + Pm[(r0 + i) * DM + c0 + j];
    __syncthreads();

    for (int i = tid * 4; i < 8192; i += 1024)
        *(float4*)(Wsm + i) = *(const float4*)(g_Ws + i);
    __syncthreads();

    // S = f @ Ws + bs + pos  -> Pm (each thread RMWs only its own elements)
    gemm_tile2(Tm, 64, Wsm, DM, 64, r0, c0, acc);
    #pragma unroll
    for (int i = 0; i < 8; i++)
        #pragma unroll
        for (int j = 0; j < 8; j++) {
            int o = (r0 + i) * DM + c0 + j;
            Pm[o] = acc[i][j] + bss[c0 + j] + Pm[o];
        }
    __syncthreads();

    for (int i = tid * 4; i < 16384; i += 1024)
        *(float4*)(Wsm + i) = *(const float4*)(g1w + i);
    __syncthreads();

    // H = relu(S @ g1 + g1b) -> Tm
    gemm_tile2(Pm, DM, Wsm, DM, DM, r0, c0, acc);
    #pragma unroll
    for (int i = 0; i < 8; i++)
        #pragma unroll
        for (int j = 0; j < 8; j++)
            Tm[(r0 + i) * DM + c0 + j] = fmaxf(acc[i][j] + bg1[c0 + j], 0.f);
    __syncthreads();

    for (int i = tid * 4; i < 16384; i += 1024)
        *(float4*)(Wsm + i) = *(const float4*)(g2w + i);
    __syncthreads();

    // A = (H @ g2 + g2b) * SCALE -> aout (pre-softmax logits, in-place later)
    gemm_tile2(Tm, DM, Wsm, DM, DM, r0, c0, acc);
    #pragma unroll
    for (int i = 0; i < 8; i++)
        #pragma unroll
        for (int j = 0; j < 8; j++)
            aout[(size_t)(p0 + r0 + i) * DM + c0 + j] =
                (acc[i][j] + bg2[c0 + j]) * SCALE_F;
}

// ---------------- k2a: per-chunk online (max,sum) over N ----------------
__global__ void k2a_stats(const float* __restrict__ aout)
{
    int tx = threadIdx.x, ty = threadIdx.y;
    int c = blockIdx.x * 32 + tx;
    int chunk = blockIdx.y;
    int b = blockIdx.z;
    const float* base = aout + (size_t)b * N_ * DM + c;
    const int rows = N_ / NCHUNK;         // 1024
    int n0 = chunk * rows;

    float m = -3.4e38f, s = 0.f;
    #pragma unroll 4
    for (int n = n0 + ty; n < n0 + rows; n += 8) {
        float a = base[(size_t)n * DM];
        float nm = fmaxf(m, a);
        s = s * __expf(m - nm) + __expf(a - nm);
        m = nm;
    }
    __shared__ float smm[8][32], sms[8][32];
    smm[ty][tx] = m; sms[ty][tx] = s;
    __syncthreads();
    if (ty == 0) {
        float M = m, S = s;
        #pragma unroll
        for (int r = 1; r < 8; r++) {
            float m2 = smm[r][tx], s2 = sms[r][tx];
            float nM = fmaxf(M, m2);
            S = S * __expf(M - nM) + s2 * __expf(m2 - nM);
            M = nM;
        }
        int o = ((b * DM + c) * NCHUNK + chunk) * 2;
        g_part[o] = M; g_part[o + 1] = S;
    }
}

// ---------------- k2b: combine chunk partials (one warp per (b,c)) ---------
__global__ void k2b_combine()
{
    int warp = (blockIdx.x * blockDim.x + threadIdx.x) >> 5;  // 0..255
    int lane = threadIdx.x & 31;
    const float* p = g_part + (size_t)warp * NCHUNK * 2;
    float m1 = p[lane * 2],       s1 = p[lane * 2 + 1];
    float m2 = p[(lane + 32) * 2], s2 = p[(lane + 32) * 2 + 1];
    float M = fmaxf(m1, m2);
    #pragma unroll
    for (int o = 16; o; o >>= 1) M = fmaxf(M, __shfl_xor_sync(0xffffffffu, M, o));
    float S = s1 * __expf(m1 - M) + s2 * __expf(m2 - M);
    #pragma unroll
    for (int o = 16; o; o >>= 1) S += __shfl_xor_sync(0xffffffffu, S, o);
    if (lane == 0) { g_ms[warp * 2] = M; g_ms[warp * 2 + 1] = 1.f / S; }
}

// ---------------- k3: softmax normalize (in place) + gate + fc2 + residual ----
__global__ void __launch_bounds__(256) k3_out(
    const float* __restrict__ feat,
    const float* __restrict__ fc2w, const float* __restrict__ fc2b,
    float* __restrict__ res, float* __restrict__ aout)
{
    extern __shared__ float smd[];
    float* fc2s = smd;            // 128*64
    float* tsm  = smd + 8192;     // 128*128
    __shared__ float msm[DM], rsm[DM], fb[64];

    int tid = threadIdx.x;
    int p0 = blockIdx.x * 128;
    int b = p0 >> 16;             // N_ = 65536

    for (int i = tid * 4; i < 8192; i += 1024)
        *(float4*)(fc2s + i) = *(const float4*)(fc2w + i);
    if (tid < DM) {
        msm[tid] = g_ms[(b * DM + tid) * 2];
        rsm[tid] = g_ms[(b * DM + tid) * 2 + 1];
    }
    if (tid < 64) fb[tid] = fc2b[tid];
    __syncthreads();

    for (int idx = tid; idx < 16384; idx += 256) {
        int c = idx & 127;
        size_t go = (size_t)p0 * DM + idx;
        float a = aout[go];
        float e = __expf(a - msm[c]) * rsm[c];
        aout[go] = e;                     // final attn output
        tsm[idx] = e * g_gv[go];          // gated values
    }
    __syncthreads();

    int tx = tid & 15, ty = tid >> 4;
    int r0 = ty * 8, c0 = tx * 4;
    unsigned long long acc2[8][2];
    #pragma unroll
    for (int i = 0; i < 8; i++) { acc2[i][0] = 0ull; acc2[i][1] = 0ull; }
    #pragma unroll 4
    for (int k = 0; k < DM; k++) {
        ulonglong2 w = *(const ulonglong2*)(fc2s + k * 64 + c0);
        #pragma unroll
        for (int i = 0; i < 8; i++) {
            float a = tsm[(r0 + i) * DM + k];
            unsigned long long aa = pk2(a, a);
            fma2(acc2[i][0], aa, w.x);
            fma2(acc2[i][1], aa, w.y);
        }
    }
    #pragma unroll
    for (int i = 0; i < 8; i++) {
        float v0, v1, v2, v3;
        upk2(acc2[i][0], v0, v1);
        upk2(acc2[i][1], v2, v3);
        size_t ro = (size_t)(p0 + r0 + i) * 64 + c0;
        res[ro + 0] = v0 + fb[c0 + 0] + feat[ro + 0];
        res[ro + 1] = v1 + fb[c0 + 1] + feat[ro + 1];
        res[ro + 2] = v2 + fb[c0 + 2] + feat[ro + 2];
        res[ro + 3] = v3 + fb[c0 + 3] + feat[ro + 3];
    }
}

// ---------------- launch ----------------
extern "C" void kernel_launch(void* const* d_in, const int* in_sizes, int n_in,
                              void* d_out, int out_size)
{
    const float* xyz  = (const float*)d_in[0];
    const float* feat = (const float*)d_in[1];
    const float* fc1w = (const float*)d_in[2];
    const float* fc1b = (const float*)d_in[3];
    const float* fc2w = (const float*)d_in[4];
    const float* fc2b = (const float*)d_in[5];
    const float* d1w  = (const float*)d_in[6];
    const float* d1b  = (const float*)d_in[7];
    const float* d2w  = (const float*)d_in[8];
    const float* d2b  = (const float*)d_in[9];
    const float* g1w  = (const float*)d_in[10];
    const float* g1b  = (const float*)d_in[11];
    const float* g2w  = (const float*)d_in[12];
    const float* g2b  = (const float*)d_in[13];
    const float* wq   = (const float*)d_in[14];
    const float* wk   = (const float*)d_in[15];
    const float* wv   = (const float*)d_in[16];

    float* res  = (float*)d_out;                       // [2,65536,64]
    float* aout = (float*)d_out + (size_t)NPTS * 64;   // [2,65536,128]

    cudaFuncSetAttribute(k1_main, cudaFuncAttributeMaxDynamicSharedMemorySize, 196608);
    cudaFuncSetAttribute(k3_out,  cudaFuncAttributeMaxDynamicSharedMemorySize, 98304);

    k0_fold<<<32, 256>>>(fc1w, fc1b, wq, wk, wv);
    k1_main<<<NPTS / 128, 256, 196608>>>(xyz, feat, d1w, d1b, d2w, d2b,
                                         g1w, g1b, g2w, g2b, aout);
    dim3 g2(DM / 32, NCHUNK, B_), b2(32, 8);
    k2a_stats<<<g2, b2>>>(aout);
    k2b_combine<<<32, 256>>>();
    k3_out<<<NPTS / 128, 256, 98304>>>(feat, fc2w, fc2b, res, aout);
}